// round 14
// baseline (speedup 1.0000x reference)
#include <cuda_runtime.h>

#define SDIM   128
#define VDIM   352           // 64*3 + 32*5
#define DIM    480
#define RPB    8             // rows per block
#define NTHR   256
#define NVTOT  (RPB * 88)    // 704 float4 in vector region
#define EPS    1e-5f

__device__ __forceinline__ float4 ldcs_f4(const float4* p) {
    float4 v;
    asm volatile("ld.global.cs.v4.f32 {%0,%1,%2,%3}, [%4];"
                 : "=f"(v.x), "=f"(v.y), "=f"(v.z), "=f"(v.w) : "l"(p));
    return v;
}
__device__ __forceinline__ void stcs_f4(float4* p, float4 v) {
    asm volatile("st.global.cs.v4.f32 [%0], {%1,%2,%3,%4};"
                 :: "l"(p), "f"(v.x), "f"(v.y), "f"(v.z), "f"(v.w));
}
__device__ __forceinline__ void stcs_f(float* p, float v) {
    asm volatile("st.global.cs.f32 [%0], %1;" :: "l"(p), "f"(v));
}

__global__ __launch_bounds__(NTHR) void eln_kernel(
    const float* __restrict__ x,
    const float* __restrict__ weight,
    const float* __restrict__ bias,
    float* __restrict__ out)
{
    __shared__ float vec[RPB][VDIM];   // 11.3 KB

    const int tid  = threadIdx.x;
    const int lane = tid & 31;
    const int wrp  = tid >> 5;         // 0..7, owns one row's scalar region
    const long long row0 = (long long)blockIdx.x * RPB;

    // ---- front-batch ALL loads ----
    const float4 w4 = __ldg((const float4*)weight + lane);
    const float4 b4 = __ldg((const float4*)bias   + lane);

    // warp w owns row (row0+w)'s scalar region: 32 x LDG.128
    const float4 sv = ldcs_f4((const float4*)(x + (row0 + wrp) * DIM) + lane);

    // vector region: 8 rows x 88 float4 = 704, strided by 256 threads
    float4 v[3];
    #pragma unroll
    for (int k = 0; k < 3; k++) {
        int idx = tid + NTHR * k;
        if (idx < NVTOT) {
            int r = idx / 88, j = idx - r * 88;
            v[k] = ldcs_f4((const float4*)(x + (row0 + r) * DIM + SDIM) + j);
        }
    }

    // ---- scalar layernorm: warp-local, no barrier ----
    float sum = sv.x + sv.y + sv.z + sv.w;
    float sq  = sv.x * sv.x + sv.y * sv.y + sv.z * sv.z + sv.w * sv.w;
    #pragma unroll
    for (int o = 16; o; o >>= 1) {
        sum += __shfl_xor_sync(0xFFFFFFFFu, sum, o);
        sq  += __shfl_xor_sync(0xFFFFFFFFu, sq,  o);
    }
    const float m  = sum * (1.0f / 128.0f);
    const float rs = rsqrtf(sq * (1.0f / 128.0f) - m * m + EPS);
    float4 so;
    so.x = (sv.x - m) * rs * w4.x + b4.x;
    so.y = (sv.y - m) * rs * w4.y + b4.y;
    so.z = (sv.z - m) * rs * w4.z + b4.z;
    so.w = (sv.w - m) * rs * w4.w + b4.w;
    stcs_f4((float4*)(out + (row0 + wrp) * DIM) + lane, so);

    // ---- stage vector region into smem (conflict-free STS.128) ----
    #pragma unroll
    for (int k = 0; k < 3; k++) {
        int idx = tid + NTHR * k;
        if (idx < NVTOT) ((float4*)vec)[idx] = v[k];
    }
    __syncthreads();   // the ONLY barrier

    // ---- segment norms: read smem strided, normalize in regs,
    //      store DIRECTLY to global (coalesced strided STG.32) ----
    #pragma unroll
    for (int k = 0; k < 3; k++) {
        int s = tid + NTHR * k;           // 0..767, exactly 3 per thread
        int r = s / 96, k96 = s - r * 96;
        float* og = out + (row0 + r) * DIM + SDIM;
        if (k96 < 64) {
            const float* p = &vec[r][3 * k96];
            float a = p[0], b = p[1], c = p[2];
            float sm = (a + b + c) * (1.0f / 3.0f);
            float d0 = a - sm, d1 = b - sm, d2 = c - sm;
            float rr = rsqrtf((d0 * d0 + d1 * d1 + d2 * d2) * (1.0f / 3.0f) + EPS);
            float* q = og + 3 * k96;
            stcs_f(q + 0, d0 * rr);
            stcs_f(q + 1, d1 * rr);
            stcs_f(q + 2, d2 * rr);
        } else {
            const float* p = &vec[r][192 + 5 * (k96 - 64)];
            float a = p[0], b = p[1], c = p[2], d = p[3], e = p[4];
            float sm = (a + b + c + d + e) * 0.2f;
            float d0 = a - sm, d1 = b - sm, d2 = c - sm, d3 = d - sm, d4 = e - sm;
            float rr = rsqrtf((d0 * d0 + d1 * d1 + d2 * d2 + d3 * d3 + d4 * d4) * 0.2f + EPS);
            float* q = og + 192 + 5 * (k96 - 64);
            stcs_f(q + 0, d0 * rr);
            stcs_f(q + 1, d1 * rr);
            stcs_f(q + 2, d2 * rr);
            stcs_f(q + 3, d3 * rr);
            stcs_f(q + 4, d4 * rr);
        }
    }
}

extern "C" void kernel_launch(void* const* d_in, const int* in_sizes, int n_in,
                              void* d_out, int out_size)
{
    const float* x      = (const float*)d_in[0];
    const float* weight = (const float*)d_in[1];
    const float* bias   = (const float*)d_in[2];
    float* out = (float*)d_out;

    const int n_rows = in_sizes[0] / DIM;   // 262144
    eln_kernel<<<n_rows / RPB, NTHR>>>(x, weight, bias, out);
}